// round 1
// baseline (speedup 1.0000x reference)
#include <cuda_runtime.h>
#include <cstdint>

// Problem constants (fixed by the dataset; n still taken from in_sizes at runtime)
#define NMAX   200704      // >= N=200000, padded
#define KNBR   64
#define TPB    128
#define SSTRIDE 65         // 64 + 1 pad word -> conflict-free LDS across warp

// Packed lookup table: (x, y, z, u) per point. Static __device__ scratch (no allocs).
__device__ float4 g_table[NMAX];
__device__ int    g_is32;   // 1 if neighbor_matrix is actually int32 data

// ---------------------------------------------------------------------------
// Detect whether the int64-declared neighbor buffer really holds int64 or was
// silently demoted to int32 by JAX. If the data is int32, interpreting pairs
// as int64 yields values >= n (hi word = some index != 0) with overwhelming
// probability over 2048 samples. Valid int64 data only holds [-1, n).
// Deterministic, branch-free w.r.t. inputs of the timed region.
// ---------------------------------------------------------------------------
__global__ void detect_kernel(const long long* __restrict__ nb, int n_elems, int n)
{
    int bad = 0;
    int lim = n_elems / 2;          // safe int64 slots even if underlying is int32
    if (lim > 2048) lim = 2048;
    for (int t = threadIdx.x; t < lim; t += blockDim.x) {
        long long v = nb[t];
        if (v < -1 || v >= (long long)n) bad = 1;
    }
    bad = __syncthreads_or(bad);
    if (threadIdx.x == 0) g_is32 = bad;
}

// ---------------------------------------------------------------------------
// Pack coords + y into float4 table (one 32B-sector gather per neighbor later)
// ---------------------------------------------------------------------------
__global__ void pack_kernel(const float* __restrict__ coords,
                            const float* __restrict__ y, int n)
{
    int i = blockIdx.x * blockDim.x + threadIdx.x;
    if (i < n) {
        g_table[i] = make_float4(coords[3 * i + 0],
                                 coords[3 * i + 1],
                                 coords[3 * i + 2],
                                 y[i]);
    }
}

// ---------------------------------------------------------------------------
// Main kernel: one thread per point.
//  Phase 1: block cooperatively stages 128x64 neighbor indices (coalesced
//           global reads, int64->int32 narrowing) into padded shared memory.
//  Phase 2: each thread streams its 64 indices from smem (conflict-free),
//           gathers float4 from the L2-resident table, accumulates the
//           symmetric 3x3 normal equations + RHS, solves via Cramer.
// ---------------------------------------------------------------------------
__global__ __launch_bounds__(TPB)
void deriv_kernel(const void* __restrict__ nb_raw,
                  float* __restrict__ out, int n)
{
    __shared__ int sidx[TPB * SSTRIDE];

    const int base = blockIdx.x * TPB;
    const int tid  = threadIdx.x;
    const bool is32 = (g_is32 != 0);

    // ---- Phase 1: coalesced staging of indices ----
    if (is32) {
        const int* __restrict__ nb32 = (const int*)nb_raw;
        #pragma unroll 4
        for (int t = tid; t < TPB * KNBR; t += TPB) {
            int pt = t >> 6;
            int k  = t & (KNBR - 1);
            int gp = base + pt;
            int v  = (gp < n) ? nb32[(long long)gp * KNBR + k] : -1;
            sidx[pt * SSTRIDE + k] = v;
        }
    } else {
        const long long* __restrict__ nb64 = (const long long*)nb_raw;
        #pragma unroll 4
        for (int t = tid; t < TPB * KNBR; t += TPB) {
            int pt = t >> 6;
            int k  = t & (KNBR - 1);
            int gp = base + pt;
            long long v = (gp < n) ? nb64[(long long)gp * KNBR + k] : -1;
            sidx[pt * SSTRIDE + k] = (int)v;
        }
    }
    __syncthreads();

    const int i = base + tid;
    if (i >= n) return;

    const float4 c = g_table[i];

    float axx = 0.f, axy = 0.f, axz = 0.f;
    float ayy = 0.f, ayz = 0.f, azz = 0.f;
    float bx  = 0.f, by  = 0.f, bz  = 0.f;

    const int* __restrict__ row = &sidx[tid * SSTRIDE];

    #pragma unroll 8
    for (int k = 0; k < KNBR; k++) {
        int j = row[k];
        if (j < 0) j = i;               // masked neighbor -> dv = du = 0
        const float4 t = g_table[j];

        float dx = t.x - c.x;
        float dy = t.y - c.y;
        float dz = t.z - c.z;
        float du = t.w - c.w;

        float r2 = fmaf(dx, dx, fmaf(dy, dy, fmaf(dz, dz, 1e-8f)));
        float w;
        asm("rcp.approx.f32 %0, %1;" : "=f"(w) : "f"(r2));

        float wdx = w * dx, wdy = w * dy, wdz = w * dz;
        axx = fmaf(wdx, dx, axx);
        axy = fmaf(wdx, dy, axy);
        axz = fmaf(wdx, dz, axz);
        ayy = fmaf(wdy, dy, ayy);
        ayz = fmaf(wdy, dz, ayz);
        azz = fmaf(wdz, dz, azz);
        bx  = fmaf(wdx, du, bx);
        by  = fmaf(wdy, du, by);
        bz  = fmaf(wdz, du, bz);
    }

    // Tikhonov regularizer
    axx += 1e-6f; ayy += 1e-6f; azz += 1e-6f;

    // Symmetric 3x3 solve via adjugate (Cramer)
    float m00 = fmaf(ayy, azz, -ayz * ayz);
    float m01 = fmaf(axz, ayz, -axy * azz);
    float m02 = fmaf(axy, ayz, -axz * ayy);
    float m11 = fmaf(axx, azz, -axz * axz);
    float m12 = fmaf(axy, axz, -axx * ayz);
    float m22 = fmaf(axx, ayy, -axy * axy);

    float det = fmaf(axx, m00, fmaf(axy, m01, axz * m02));
    float inv;
    asm("rcp.approx.f32 %0, %1;" : "=f"(inv) : "f"(det));

    float gx = fmaf(m00, bx, fmaf(m01, by, m02 * bz)) * inv;
    float gy = fmaf(m01, bx, fmaf(m11, by, m12 * bz)) * inv;
    float gz = fmaf(m02, bx, fmaf(m12, by, m22 * bz)) * inv;

    out[3 * i + 0] = gx;
    out[3 * i + 1] = gy;
    out[3 * i + 2] = gz;
}

// ---------------------------------------------------------------------------
extern "C" void kernel_launch(void* const* d_in, const int* in_sizes, int n_in,
                              void* d_out, int out_size)
{
    const float* coords = (const float*)d_in[0];   // [N, 3] float32
    const void*  nb     = d_in[1];                 // [N, 64] int64 (or demoted int32)
    const float* yv     = (const float*)d_in[2];   // [N, 1] float32
    float*       out    = (float*)d_out;           // [N, 3] float32

    const int n = in_sizes[0] / 3;

    detect_kernel<<<1, 256>>>((const long long*)nb, in_sizes[1], n);
    pack_kernel<<<(n + 255) / 256, 256>>>(coords, yv, n);
    deriv_kernel<<<(n + TPB - 1) / TPB, TPB>>>(nb, out, n);
}

// round 2
// speedup vs baseline: 1.0047x; 1.0047x over previous
#include <cuda_runtime.h>
#include <cstdint>

#define NMAX   200704      // >= N=200000
#define KNBR   64
#define TPB    128
#define SSTRIDE 65         // 64 + 1 pad -> conflict-free LDS across warp

__device__ float4 g_table[NMAX];
__device__ int    g_is32;   // 1 if neighbor_matrix is actually int32 data

// ---------------------------------------------------------------------------
// pack: build (x,y,z,u) float4 table. Block 0 additionally classifies the
// neighbor buffer dtype (JAX may silently demote int64->int32): int32 data
// read as int64 yields values outside [-1, n) with overwhelming probability
// over 2048 samples. Deterministic; same result every replay.
// ---------------------------------------------------------------------------
__global__ void pack_kernel(const float* __restrict__ coords,
                            const float* __restrict__ y,
                            const long long* __restrict__ nb,
                            int nb_elems, int n)
{
    int i = blockIdx.x * blockDim.x + threadIdx.x;
    if (i < n) {
        g_table[i] = make_float4(coords[3 * i + 0],
                                 coords[3 * i + 1],
                                 coords[3 * i + 2],
                                 y[i]);
    }
    if (blockIdx.x == 0) {
        int bad = 0;
        int lim = nb_elems / 2;
        if (lim > 2048) lim = 2048;
        for (int t = threadIdx.x; t < lim; t += blockDim.x) {
            long long v = nb[t];
            if (v < -1 || v >= (long long)n) bad = 1;
        }
        bad = __syncthreads_or(bad);
        if (threadIdx.x == 0) g_is32 = bad;
    }
}

// ---------------------------------------------------------------------------
// deriv: one thread per point.
//  Phase 1: block stages 128x64 neighbor indices via wide vector loads,
//           stored into padded smem with a PERMUTED within-row layout
//           (element pairs go to k and k+32) -> conflict-free STS.
//           Permutation is legal: the neighbor sum is order-independent.
//  Phase 2: each thread streams 64 indices (conflict-free LDS), gathers
//           float4 from the L2-resident table, accumulates the symmetric
//           3x3 normal equations + RHS, solves via Cramer/adjugate.
// ---------------------------------------------------------------------------
__global__ __launch_bounds__(TPB)
void deriv_kernel(const void* __restrict__ nb_raw,
                  float* __restrict__ out, int n)
{
    __shared__ int sidx[TPB * SSTRIDE];

    const int base = blockIdx.x * TPB;
    const int tid  = threadIdx.x;
    const bool is32 = (g_is32 != 0);

    // ---- Phase 1: coalesced vectorized staging ----
    if (is32) {
        const int4* __restrict__ nb4 = (const int4*)nb_raw;
        #pragma unroll
        for (int t = tid; t < TPB * KNBR / 4; t += TPB) {   // 16 iters
            int pt = t >> 4;
            int k  = t & 15;
            int gp = base + pt;
            int4 v = make_int4(-1, -1, -1, -1);
            if (gp < n) v = nb4[(size_t)gp * 16 + k];
            int* r = &sidx[pt * SSTRIDE];
            r[k]      = v.x;
            r[k + 16] = v.y;
            r[k + 32] = v.z;
            r[k + 48] = v.w;
        }
    } else {
        const longlong2* __restrict__ nb2 = (const longlong2*)nb_raw;
        #pragma unroll
        for (int t = tid; t < TPB * KNBR / 2; t += TPB) {   // 32 iters
            int pt = t >> 5;
            int k  = t & 31;
            int gp = base + pt;
            longlong2 v = make_longlong2(-1, -1);
            if (gp < n) v = nb2[(size_t)gp * 32 + k];
            int* r = &sidx[pt * SSTRIDE];
            r[k]      = (int)v.x;
            r[k + 32] = (int)v.y;
        }
    }
    __syncthreads();

    const int i = base + tid;
    if (i >= n) return;

    const float4 c = g_table[i];

    float axx = 0.f, axy = 0.f, axz = 0.f;
    float ayy = 0.f, ayz = 0.f, azz = 0.f;
    float bx  = 0.f, by  = 0.f, bz  = 0.f;

    const int* __restrict__ row = &sidx[tid * SSTRIDE];

    #pragma unroll 8
    for (int k = 0; k < KNBR; k++) {
        int j = row[k];
        if (j < 0) j = i;               // masked neighbor -> dv = du = 0
        const float4 t = __ldg(&g_table[j]);

        float dx = t.x - c.x;
        float dy = t.y - c.y;
        float dz = t.z - c.z;
        float du = t.w - c.w;

        float r2 = fmaf(dx, dx, fmaf(dy, dy, fmaf(dz, dz, 1e-8f)));
        float w;
        asm("rcp.approx.f32 %0, %1;" : "=f"(w) : "f"(r2));

        float wdx = w * dx, wdy = w * dy, wdz = w * dz;
        axx = fmaf(wdx, dx, axx);
        axy = fmaf(wdx, dy, axy);
        axz = fmaf(wdx, dz, axz);
        ayy = fmaf(wdy, dy, ayy);
        ayz = fmaf(wdy, dz, ayz);
        azz = fmaf(wdz, dz, azz);
        bx  = fmaf(wdx, du, bx);
        by  = fmaf(wdy, du, by);
        bz  = fmaf(wdz, du, bz);
    }

    // Tikhonov regularizer
    axx += 1e-6f; ayy += 1e-6f; azz += 1e-6f;

    // Symmetric 3x3 solve via adjugate (Cramer)
    float m00 = fmaf(ayy, azz, -ayz * ayz);
    float m01 = fmaf(axz, ayz, -axy * azz);
    float m02 = fmaf(axy, ayz, -axz * ayy);
    float m11 = fmaf(axx, azz, -axz * axz);
    float m12 = fmaf(axy, axz, -axx * ayz);
    float m22 = fmaf(axx, ayy, -axy * axy);

    float det = fmaf(axx, m00, fmaf(axy, m01, axz * m02));
    float inv;
    asm("rcp.approx.f32 %0, %1;" : "=f"(inv) : "f"(det));

    float gx = fmaf(m00, bx, fmaf(m01, by, m02 * bz)) * inv;
    float gy = fmaf(m01, bx, fmaf(m11, by, m12 * bz)) * inv;
    float gz = fmaf(m02, bx, fmaf(m12, by, m22 * bz)) * inv;

    out[3 * i + 0] = gx;
    out[3 * i + 1] = gy;
    out[3 * i + 2] = gz;
}

// ---------------------------------------------------------------------------
extern "C" void kernel_launch(void* const* d_in, const int* in_sizes, int n_in,
                              void* d_out, int out_size)
{
    const float* coords = (const float*)d_in[0];   // [N, 3] float32
    const void*  nb     = d_in[1];                 // [N, 64] int64 (maybe demoted int32)
    const float* yv     = (const float*)d_in[2];   // [N, 1] float32
    float*       out    = (float*)d_out;           // [N, 3] float32

    const int n = in_sizes[0] / 3;

    pack_kernel<<<(n + 255) / 256, 256>>>(coords, yv,
                                          (const long long*)nb, in_sizes[1], n);
    deriv_kernel<<<(n + TPB - 1) / TPB, TPB>>>(nb, out, n);
}

// round 3
// speedup vs baseline: 1.7836x; 1.7753x over previous
#include <cuda_runtime.h>
#include <cstdint>

#define NMAX   200704      // >= N=200000, bounds all clamped gathers
#define KNBR   64
#define TPB    128
#define HALF   32          // neighbors staged per phase
#define SST    33          // 32 + 1 pad words -> conflict-free LDS per warp

__device__ float4 g_table[NMAX];
__device__ int    g_is32;   // 1 if neighbor_matrix is actually int32 data

// ---------------------------------------------------------------------------
// pack: build (x,y,z,u) float4 table. Block 0 also classifies the neighbor
// buffer dtype (JAX silently demotes int64->int32 without x64): int32 data
// read as int64 yields values outside [-1, n) with overwhelming probability
// over 2048 samples. Deterministic every replay.
// ---------------------------------------------------------------------------
__global__ void pack_kernel(const float* __restrict__ coords,
                            const float* __restrict__ y,
                            const long long* __restrict__ nb,
                            int nb_elems, int n)
{
    int i = blockIdx.x * blockDim.x + threadIdx.x;
    if (i < n) {
        g_table[i] = make_float4(coords[3 * i + 0],
                                 coords[3 * i + 1],
                                 coords[3 * i + 2],
                                 y[i]);
    }
    if (blockIdx.x == 0) {
        int bad = 0;
        int lim = nb_elems / 2;
        if (lim > 2048) lim = 2048;
        for (int t = threadIdx.x; t < lim; t += blockDim.x) {
            long long v = nb[t];
            if (v < -1 || v >= (long long)n) bad = 1;
        }
        bad = __syncthreads_or(bad);
        if (threadIdx.x == 0) g_is32 = bad;
    }
}

// ---------------------------------------------------------------------------
// deriv: one thread per point, TWO stage->compute phases (32 neighbors each)
// to halve smem (16.9KB) and, with the 64-reg cap from __launch_bounds__,
// reach 8 resident blocks (32 warps/SM) — this kernel is latency-bound on
// L2 gathers, so occupancy is the binding resource.
// All threads run both phases (barriers inside); only the final store is
// guarded by i < n. Clamped gathers stay inside g_table[NMAX] (zero-init).
// ---------------------------------------------------------------------------
__global__ __launch_bounds__(TPB, 8)
void deriv_kernel(const void* __restrict__ nb_raw,
                  float* __restrict__ out, int n)
{
    __shared__ int sidx[TPB * SST];

    const int base = blockIdx.x * TPB;
    const int tid  = threadIdx.x;
    const bool is32 = (g_is32 != 0);
    const int i = base + tid;                 // < 1563*128 = 200064 < NMAX

    const float4 c = g_table[i];

    float axx = 0.f, axy = 0.f, axz = 0.f;
    float ayy = 0.f, ayz = 0.f, azz = 0.f;
    float bx  = 0.f, by  = 0.f, bz  = 0.f;

    #pragma unroll
    for (int half = 0; half < 2; half++) {
        __syncthreads();   // protect smem from previous phase's readers

        // ---- stage 32 indices/point, coalesced wide loads, permuted STS ----
        if (is32) {
            const int4* __restrict__ nb4 = (const int4*)nb_raw;
            #pragma unroll
            for (int t = tid; t < TPB * HALF / 4; t += TPB) {   // 8 iters
                int pt = t >> 3, k4 = t & 7;
                int gp = base + pt;
                int4 v = make_int4(-1, -1, -1, -1);
                if (gp < n) v = nb4[(size_t)gp * 16 + half * 8 + k4];
                int* r = &sidx[pt * SST];
                r[k4]      = v.x;
                r[k4 + 8]  = v.y;
                r[k4 + 16] = v.z;
                r[k4 + 24] = v.w;
            }
        } else {
            const longlong2* __restrict__ nb2 = (const longlong2*)nb_raw;
            #pragma unroll
            for (int t = tid; t < TPB * HALF / 2; t += TPB) {   // 16 iters
                int pt = t >> 4, k2 = t & 15;
                int gp = base + pt;
                longlong2 v = make_longlong2(-1, -1);
                if (gp < n) v = nb2[(size_t)gp * 32 + half * 16 + k2];
                int* r = &sidx[pt * SST];
                r[k2]      = (int)v.x;
                r[k2 + 16] = (int)v.y;
            }
        }
        __syncthreads();

        // ---- gather + accumulate (order-independent sum; permuted order OK) ----
        const int* __restrict__ row = &sidx[tid * SST];
        #pragma unroll 8
        for (int k = 0; k < HALF; k++) {
            int j = row[k];
            if (j < 0) j = i;               // masked neighbor -> dv = du = 0
            const float4 t = __ldg(&g_table[j]);

            float dx = t.x - c.x;
            float dy = t.y - c.y;
            float dz = t.z - c.z;
            float du = t.w - c.w;

            float r2 = fmaf(dx, dx, fmaf(dy, dy, fmaf(dz, dz, 1e-8f)));
            float w;
            asm("rcp.approx.f32 %0, %1;" : "=f"(w) : "f"(r2));

            float wdx = w * dx, wdy = w * dy, wdz = w * dz;
            axx = fmaf(wdx, dx, axx);
            axy = fmaf(wdx, dy, axy);
            axz = fmaf(wdx, dz, axz);
            ayy = fmaf(wdy, dy, ayy);
            ayz = fmaf(wdy, dz, ayz);
            azz = fmaf(wdz, dz, azz);
            bx  = fmaf(wdx, du, bx);
            by  = fmaf(wdy, du, by);
            bz  = fmaf(wdz, du, bz);
        }
    }

    // Tikhonov regularizer
    axx += 1e-6f; ayy += 1e-6f; azz += 1e-6f;

    // Symmetric 3x3 solve via adjugate (Cramer)
    float m00 = fmaf(ayy, azz, -ayz * ayz);
    float m01 = fmaf(axz, ayz, -axy * azz);
    float m02 = fmaf(axy, ayz, -axz * ayy);
    float m11 = fmaf(axx, azz, -axz * axz);
    float m12 = fmaf(axy, axz, -axx * ayz);
    float m22 = fmaf(axx, ayy, -axy * axy);

    float det = fmaf(axx, m00, fmaf(axy, m01, axz * m02));
    float inv;
    asm("rcp.approx.f32 %0, %1;" : "=f"(inv) : "f"(det));

    float gx = fmaf(m00, bx, fmaf(m01, by, m02 * bz)) * inv;
    float gy = fmaf(m01, bx, fmaf(m11, by, m12 * bz)) * inv;
    float gz = fmaf(m02, bx, fmaf(m12, by, m22 * bz)) * inv;

    if (i < n) {
        out[3 * i + 0] = gx;
        out[3 * i + 1] = gy;
        out[3 * i + 2] = gz;
    }
}

// ---------------------------------------------------------------------------
extern "C" void kernel_launch(void* const* d_in, const int* in_sizes, int n_in,
                              void* d_out, int out_size)
{
    const float* coords = (const float*)d_in[0];   // [N, 3] float32
    const void*  nb     = d_in[1];                 // [N, 64] int64 (demoted int32 in practice)
    const float* yv     = (const float*)d_in[2];   // [N, 1] float32
    float*       out    = (float*)d_out;           // [N, 3] float32

    const int n = in_sizes[0] / 3;

    pack_kernel<<<(n + 255) / 256, 256>>>(coords, yv,
                                          (const long long*)nb, in_sizes[1], n);
    deriv_kernel<<<(n + TPB - 1) / TPB, TPB>>>(nb, out, n);
}

// round 5
// speedup vs baseline: 1.8981x; 1.0642x over previous
#include <cuda_runtime.h>
#include <cstdint>

#define NMAX   200704      // >= N=200000, bounds all clamped gathers
#define KNBR   64
#define TPB    128
#define PPB    64          // points per block (2 threads/point)
#define SROW   66          // smem row stride (words) per point
#define HOFF   33          // offset of second half within a row

__device__ float4 g_table[NMAX];
__device__ int    g_is32;   // 1 if neighbor_matrix is actually int32 data

// ---------------------------------------------------------------------------
// pack: build (x,y,z,u) float4 table. Block 0 also classifies the neighbor
// buffer dtype (JAX silently demotes int64->int32 without x64): int32 data
// read as int64 yields values outside [-1, n) with overwhelming probability
// over 2048 samples. Deterministic every replay.
// ---------------------------------------------------------------------------
__global__ void pack_kernel(const float* __restrict__ coords,
                            const float* __restrict__ y,
                            const long long* __restrict__ nb,
                            int nb_elems, int n)
{
    int i = blockIdx.x * blockDim.x + threadIdx.x;
    if (i < n) {
        g_table[i] = make_float4(coords[3 * i + 0],
                                 coords[3 * i + 1],
                                 coords[3 * i + 2],
                                 y[i]);
    }
    if (blockIdx.x == 0) {
        int bad = 0;
        int lim = nb_elems / 2;
        if (lim > 2048) lim = 2048;
        for (int t = threadIdx.x; t < lim; t += blockDim.x) {
            long long v = nb[t];
            if (v < -1 || v >= (long long)n) bad = 1;
        }
        bad = __syncthreads_or(bad);
        if (threadIdx.x == 0) g_is32 = bad;
    }
}

// ---------------------------------------------------------------------------
// deriv: TWO THREADS per point (64 points / 128-thread block). Each thread
// gathers+accumulates 32 of the point's 64 neighbors; one shfl.bfly(1) round
// combines the 9 partial sums; the even lane solves the 3x3 system.
// Rationale: kernel is L1-wavefront-bound; halving per-block work raises the
// grid from 1563 to 3125 blocks, cutting wave-quantization loss (1.51x->1.14x
// over the ideal schedule) while keeping gather wavefronts at the floor.
// Smem: [64 points][66 words]; thread (p,h) reads words h*33 + m, m=0..31.
// Bank = (2p + h + m) mod 32 -> bijective over a warp => conflict-free LDS.
// ---------------------------------------------------------------------------
__global__ __launch_bounds__(TPB, 8)
void deriv_kernel(const void* __restrict__ nb_raw,
                  float* __restrict__ out, int n)
{
    __shared__ int sidx[PPB * SROW];

    const int tid  = threadIdx.x;
    const int base = blockIdx.x * PPB;
    const bool is32 = (g_is32 != 0);

    const int p    = tid >> 1;           // local point 0..63
    const int half = tid & 1;            // which 32 neighbors
    const int i    = base + p;           // global point (< NMAX by grid bound)

    // ---- stage 64x64 indices, fully coalesced wide loads ----
    if (is32) {
        const int4* __restrict__ nb4 = (const int4*)nb_raw;
        const size_t gbase = (size_t)blockIdx.x * (PPB * KNBR / 4);
        #pragma unroll
        for (int jj = 0; jj < 8; jj++) {
            int l  = tid + jj * TPB;         // 0..1023
            int pt = l >> 4;                 // local point
            int c4 = l & 15;                 // which int4 in the row
            int4 v = make_int4(-1, -1, -1, -1);
            if (base + pt < n) v = nb4[gbase + l];
            int hh = c4 >> 3;                // half
            int mm = (c4 & 7) * 4;           // word within half
            int* r = &sidx[pt * SROW + hh * HOFF + mm];
            r[0] = v.x; r[1] = v.y; r[2] = v.z; r[3] = v.w;
        }
    } else {
        const longlong2* __restrict__ nb2 = (const longlong2*)nb_raw;
        const size_t gbase = (size_t)blockIdx.x * (PPB * KNBR / 2);
        #pragma unroll
        for (int jj = 0; jj < 16; jj++) {
            int l  = tid + jj * TPB;         // 0..2047
            int pt = l >> 5;
            int c2 = l & 31;
            longlong2 v = make_longlong2(-1, -1);
            if (base + pt < n) v = nb2[gbase + l];
            int hh = c2 >> 4;
            int mm = (c2 & 15) * 2;
            int* r = &sidx[pt * SROW + hh * HOFF + mm];
            r[0] = (int)v.x; r[1] = (int)v.y;
        }
    }
    __syncthreads();

    const float4 c = g_table[i];

    float axx = 0.f, axy = 0.f, axz = 0.f;
    float ayy = 0.f, ayz = 0.f, azz = 0.f;
    float bx  = 0.f, by  = 0.f, bz  = 0.f;

    const int* __restrict__ row = &sidx[p * SROW + half * HOFF];

    #pragma unroll 8
    for (int k = 0; k < 32; k++) {
        int j = row[k];
        if (j < 0) j = i;                    // masked neighbor -> dv = du = 0
        const float4 t = __ldg(&g_table[j]);

        float dx = t.x - c.x;
        float dy = t.y - c.y;
        float dz = t.z - c.z;
        float du = t.w - c.w;

        float r2 = fmaf(dx, dx, fmaf(dy, dy, fmaf(dz, dz, 1e-8f)));
        float w;
        asm("rcp.approx.f32 %0, %1;" : "=f"(w) : "f"(r2));

        float wdx = w * dx, wdy = w * dy, wdz = w * dz;
        axx = fmaf(wdx, dx, axx);
        axy = fmaf(wdx, dy, axy);
        axz = fmaf(wdx, dz, axz);
        ayy = fmaf(wdy, dy, ayy);
        ayz = fmaf(wdy, dz, ayz);
        azz = fmaf(wdz, dz, azz);
        bx  = fmaf(wdx, du, bx);
        by  = fmaf(wdy, du, by);
        bz  = fmaf(wdz, du, bz);
    }

    // ---- pair reduction: lanes 2a and 2a+1 combine (xor 1) ----
    const unsigned FULL = 0xffffffffu;
    axx += __shfl_xor_sync(FULL, axx, 1);
    axy += __shfl_xor_sync(FULL, axy, 1);
    axz += __shfl_xor_sync(FULL, axz, 1);
    ayy += __shfl_xor_sync(FULL, ayy, 1);
    ayz += __shfl_xor_sync(FULL, ayz, 1);
    azz += __shfl_xor_sync(FULL, azz, 1);
    bx  += __shfl_xor_sync(FULL, bx , 1);
    by  += __shfl_xor_sync(FULL, by , 1);
    bz  += __shfl_xor_sync(FULL, bz , 1);

    if (half == 0 && i < n) {
        // Tikhonov regularizer
        axx += 1e-6f; ayy += 1e-6f; azz += 1e-6f;

        // Symmetric 3x3 solve via adjugate (Cramer)
        float m00 = fmaf(ayy, azz, -ayz * ayz);
        float m01 = fmaf(axz, ayz, -axy * azz);
        float m02 = fmaf(axy, ayz, -axz * ayy);
        float m11 = fmaf(axx, azz, -axz * axz);
        float m12 = fmaf(axy, axz, -axx * ayz);
        float m22 = fmaf(axx, ayy, -axy * axy);

        float det = fmaf(axx, m00, fmaf(axy, m01, axz * m02));
        float inv;
        asm("rcp.approx.f32 %0, %1;" : "=f"(inv) : "f"(det));

        float gx = fmaf(m00, bx, fmaf(m01, by, m02 * bz)) * inv;
        float gy = fmaf(m01, bx, fmaf(m11, by, m12 * bz)) * inv;
        float gz = fmaf(m02, bx, fmaf(m12, by, m22 * bz)) * inv;

        out[3 * i + 0] = gx;
        out[3 * i + 1] = gy;
        out[3 * i + 2] = gz;
    }
}

// ---------------------------------------------------------------------------
extern "C" void kernel_launch(void* const* d_in, const int* in_sizes, int n_in,
                              void* d_out, int out_size)
{
    const float* coords = (const float*)d_in[0];   // [N, 3] float32
    const void*  nb     = d_in[1];                 // [N, 64] int64 (demoted int32 in practice)
    const float* yv     = (const float*)d_in[2];   // [N, 1] float32
    float*       out    = (float*)d_out;           // [N, 3] float32

    const int n = in_sizes[0] / 3;

    pack_kernel<<<(n + 255) / 256, 256>>>(coords, yv,
                                          (const long long*)nb, in_sizes[1], n);
    deriv_kernel<<<(n + PPB - 1) / PPB, TPB>>>(nb, out, n);
}